// round 16
// baseline (speedup 1.0000x reference)
#include <cuda_runtime.h>
#include <stdint.h>

typedef unsigned long long u64;

#define NQ     14
#define DIM    16384
#define BATCH  128
#define NGATES 26
#define NOBS   11
#define ENC    390
#define INDIM  784
#define CT     512

// smem u64-index layout
#define HOFF_I   16384
#define HDIAG_I  (HOFF_I + 1320)
#define USP_I    (HDIAG_I + 176)
#define RY_I     (USP_I + 832)
#define HOFF_OFF  (HOFF_I * 8)
#define HDIAG_OFF (HDIAG_I * 8)
#define USP_OFF   (USP_I * 8)
#define SMEM_BYTES (RY_I * 8 + (84 + 176 + 16) * 4)

// ---------------- device scratch ----------------
__device__ float  g_enc[BATCH * ENC];
__device__ float2 g_U[NGATES * BATCH * 16];

// ---------------- packed f32x2 helpers ----------------
__device__ __forceinline__ u64 pk2(float lo, float hi) {
    u64 r; asm("mov.b64 %0,{%1,%2};" : "=l"(r) : "f"(lo), "f"(hi)); return r;
}
__device__ __forceinline__ void upk(u64 v, float& lo, float& hi) {
    asm("mov.b64 {%0,%1},%2;" : "=f"(lo), "=f"(hi) : "l"(v));
}
__device__ __forceinline__ u64 f2fma(u64 a, u64 b, u64 c) {
    u64 d; asm("fma.rn.f32x2 %0,%1,%2,%3;" : "=l"(d) : "l"(a), "l"(b), "l"(c)); return d;
}
__device__ __forceinline__ u64 f2mul(u64 a, u64 b) {
    u64 d; asm("mul.rn.f32x2 %0,%1,%2;" : "=l"(d) : "l"(a), "l"(b)); return d;
}
__device__ __forceinline__ u64 f2add(u64 a, u64 b) {
    u64 d; asm("add.rn.f32x2 %0,%1,%2;" : "=l"(d) : "l"(a), "l"(b)); return d;
}
// (re,im) -> (-im, re)
__device__ __forceinline__ u64 iswap(u64 v) {
    u64 r; asm("{.reg .f32 lo,hi,nh; mov.b64 {lo,hi},%1; neg.f32 nh,hi; mov.b64 %0,{nh,lo};}"
               : "=l"(r) : "l"(v)); return r;
}
// (re,im) -> (im, -re)
__device__ __forceinline__ u64 jswap(u64 v) {
    u64 r; asm("{.reg .f32 lo,hi,nl; mov.b64 {lo,hi},%1; neg.f32 nl,lo; mov.b64 %0,{hi,nl};}"
               : "=l"(r) : "l"(v)); return r;
}
__device__ __forceinline__ u64 sp_lo(u64 v) {
    u64 r; asm("{.reg .f32 lo,hi; mov.b64 {lo,hi},%1; mov.b64 %0,{lo,lo};}"
               : "=l"(r) : "l"(v)); return r;
}
__device__ __forceinline__ u64 sp_hi(u64 v) {
    u64 r; asm("{.reg .f32 lo,hi; mov.b64 {lo,hi},%1; mov.b64 %0,{hi,hi};}"
               : "=l"(r) : "l"(v)); return r;
}

// ---------------- shared-memory asm accessors ----------------
__device__ __forceinline__ uint32_t smem_u32(const void* p) {
    uint32_t a;
    asm("{.reg .u64 t; cvta.to.shared.u64 t,%1; cvt.u32.u64 %0,t;}" : "=r"(a) : "l"(p));
    return a;
}
__device__ __forceinline__ u64 lds64v(uint32_t a) {
    u64 r; asm volatile("ld.shared.b64 %0,[%1];" : "=l"(r) : "r"(a)); return r;
}
__device__ __forceinline__ void lds128v(uint32_t a, u64& x, u64& y) {
    asm volatile("ld.shared.v2.b64 {%0,%1},[%2];" : "=l"(x), "=l"(y) : "r"(a));
}
__device__ __forceinline__ void sts128v(uint32_t a, u64 x, u64 y) {
    asm volatile("st.shared.v2.b64 [%0],{%1,%2};" :: "r"(a), "l"(x), "l"(y) : "memory");
}

// ---------------- Pauli table ----------------
__constant__ signed char PT[60][4] = {
 {0,1,1,0},{1,0,1,0},{2,3,1,0},{3,2,1,0},
 {0,1,0,-1},{1,0,0,1},{2,3,0,-1},{3,2,0,1},
 {0,0,1,0},{1,1,-1,0},{2,2,1,0},{3,3,-1,0},
 {0,2,1,0},{1,3,1,0},{2,0,1,0},{3,1,1,0},
 {0,3,1,0},{1,2,1,0},{2,1,1,0},{3,0,1,0},
 {0,3,0,-1},{1,2,0,1},{2,1,0,-1},{3,0,0,1},
 {0,2,1,0},{1,3,-1,0},{2,0,1,0},{3,1,-1,0},
 {0,2,0,-1},{1,3,0,-1},{2,0,0,1},{3,1,0,1},
 {0,3,0,-1},{1,2,0,-1},{2,1,0,1},{3,0,0,1},
 {0,3,-1,0},{1,2,1,0},{2,1,1,0},{3,0,-1,0},
 {0,2,0,-1},{1,3,0,1},{2,0,0,1},{3,1,0,-1},
 {0,0,1,0},{1,1,1,0},{2,2,-1,0},{3,3,-1,0},
 {0,1,1,0},{1,0,1,0},{2,3,-1,0},{3,2,-1,0},
 {0,1,0,-1},{1,0,0,1},{2,3,0,1},{3,2,0,-1},
 {0,0,1,0},{1,1,-1,0},{2,2,-1,0},{3,3,1,0},
};

// ---------------- kernel 1: encode (196 blocks, 8 j per block, 2 rows per warp) ----------------
__global__ void encode_kernel(const float* __restrict__ x,
                              const float* __restrict__ W,
                              const float* __restrict__ bv) {
    __shared__ float4 wrow[8][INDIM / 4];          // 25 KB
    int jt = blockIdx.x % 49;
    int bt = blockIdx.x / 49;
    int j0 = jt * 8;
    for (int i = threadIdx.x; i < 8 * (INDIM / 4); i += CT) {
        int jj = i / (INDIM / 4), kk = i % (INDIM / 4);
        int j = j0 + jj; if (j >= ENC) j = ENC - 1;
        wrow[jj][kk] = ((const float4*)(W + (size_t)j * INDIM))[kk];
    }
    __syncthreads();
    int warp = threadIdx.x >> 5, lane = threadIdx.x & 31;
    int b0 = bt * 32 + warp * 2;                   // 4 b-tiles x 16 warps x 2 = 128
    const float4* xr0 = (const float4*)(x + (size_t)b0 * INDIM);
    const float4* xr1 = (const float4*)(x + (size_t)(b0 + 1) * INDIM);
    float4 xa0[7], xa1[7];
    #pragma unroll
    for (int i = 0; i < 7; i++) {
        int idx = lane + 32 * i;
        bool ok = idx < INDIM / 4;
        xa0[i] = ok ? __ldg(xr0 + idx) : make_float4(0.f, 0.f, 0.f, 0.f);
        xa1[i] = ok ? __ldg(xr1 + idx) : make_float4(0.f, 0.f, 0.f, 0.f);
    }
    float acc0[8] = {0.f, 0.f, 0.f, 0.f, 0.f, 0.f, 0.f, 0.f};
    float acc1[8] = {0.f, 0.f, 0.f, 0.f, 0.f, 0.f, 0.f, 0.f};
    #pragma unroll
    for (int jj = 0; jj < 8; jj++) {
        #pragma unroll
        for (int i = 0; i < 7; i++) {
            int idx = lane + 32 * i;
            if (idx < INDIM / 4) {
                float4 wa = wrow[jj][idx];
                acc0[jj] = fmaf(xa0[i].x, wa.x, acc0[jj]);
                acc0[jj] = fmaf(xa0[i].y, wa.y, acc0[jj]);
                acc0[jj] = fmaf(xa0[i].z, wa.z, acc0[jj]);
                acc0[jj] = fmaf(xa0[i].w, wa.w, acc0[jj]);
                acc1[jj] = fmaf(xa1[i].x, wa.x, acc1[jj]);
                acc1[jj] = fmaf(xa1[i].y, wa.y, acc1[jj]);
                acc1[jj] = fmaf(xa1[i].z, wa.z, acc1[jj]);
                acc1[jj] = fmaf(xa1[i].w, wa.w, acc1[jj]);
            }
        }
    }
    #pragma unroll
    for (int off = 16; off; off >>= 1) {
        #pragma unroll
        for (int jj = 0; jj < 8; jj++) {
            acc0[jj] += __shfl_xor_sync(0xffffffffu, acc0[jj], off);
            acc1[jj] += __shfl_xor_sync(0xffffffffu, acc1[jj], off);
        }
    }
    if (lane == 0) {
        #pragma unroll
        for (int jj = 0; jj < 8; jj++) {
            int j = j0 + jj;
            if (j < ENC) {
                g_enc[b0 * ENC + j]       = acc0[jj] + bv[j];
                g_enc[(b0 + 1) * ENC + j] = acc1[jj] + bv[j];
            }
        }
    }
}

// ---------------- kernel 2: SU(4) expm ----------------
__device__ __forceinline__ float2 cfma(float2 a, float2 b, float2 c) {
    c.x = fmaf(a.x, b.x, c.x); c.x = fmaf(-a.y, b.y, c.x);
    c.y = fmaf(a.x, b.y, c.y); c.y = fmaf( a.y, b.x, c.y);
    return c;
}
__device__ __forceinline__ void cmm4(const float2* A, const float2* B, float2* C) {
    #pragma unroll
    for (int r = 0; r < 4; r++)
        #pragma unroll
        for (int c = 0; c < 4; c++) {
            float2 acc = make_float2(0.f, 0.f);
            #pragma unroll
            for (int k = 0; k < 4; k++) acc = cfma(A[r*4+k], B[k*4+c], acc);
            C[r*4+c] = acc;
        }
}

__global__ void su4_kernel() {
    int id = blockIdx.x * blockDim.x + threadIdx.x;
    if (id >= NGATES * BATCH) return;
    int g = id >> 7, b = id & 127;
    const float* th = g_enc + b * ENC + g * 15;

    float2 H[16];
    #pragma unroll
    for (int e = 0; e < 16; e++) H[e] = make_float2(0.f, 0.f);
    #pragma unroll
    for (int m = 0; m < 15; m++) {
        float t = th[m];
        #pragma unroll
        for (int e = 0; e < 4; e++) {
            int r = PT[m*4+e][0], c = PT[m*4+e][1];
            H[r*4+c].x = fmaf(t, (float)PT[m*4+e][2], H[r*4+c].x);
            H[r*4+c].y = fmaf(t, (float)PT[m*4+e][3], H[r*4+c].y);
        }
    }
    float fro2 = 0.f;
    #pragma unroll
    for (int e = 0; e < 16; e++) fro2 += H[e].x*H[e].x + H[e].y*H[e].y;
    float fro = sqrtf(fro2);
    int s = 0; float sc = 1.f;
    while (fro * sc > 0.5f && s < 30) { sc *= 0.5f; s++; }

    float2 Am[16];
    #pragma unroll
    for (int e = 0; e < 16; e++) Am[e] = make_float2(-H[e].y * sc, H[e].x * sc);

    float2 R[16], Tm[16];
    #pragma unroll
    for (int e = 0; e < 16; e++) R[e] = make_float2((e % 5 == 0) ? 1.f : 0.f, 0.f);
    for (int j = 9; j >= 1; j--) {
        cmm4(Am, R, Tm);
        float inv = 1.f / (float)j;
        #pragma unroll
        for (int e = 0; e < 16; e++)
            R[e] = make_float2(fmaf(Tm[e].x, inv, (e % 5 == 0) ? 1.f : 0.f), Tm[e].y * inv);
    }
    for (int t2 = 0; t2 < s; t2++) {
        cmm4(R, R, Tm);
        #pragma unroll
        for (int e = 0; e < 16; e++) R[e] = Tm[e];
    }
    #pragma unroll
    for (int e = 0; e < 16; e++) g_U[id * 16 + e] = R[e];
}

// ---------------- packed RY pair ----------------
__device__ __forceinline__ void rypair(u64& a, u64& b, u64 c2, u64 s2, u64 ns2) {
    u64 na = f2fma(ns2, b, f2mul(c2, a));
    u64 nb = f2fma(c2,  b, f2mul(s2, a));
    a = na; b = nb;
}
__device__ __forceinline__ void ry16p(u64* v, int m, u64 c2, u64 s2, u64 ns2) {
    #pragma unroll
    for (int k = 0; k < 16; k++) if (!(k & m)) rypair(v[k], v[k | m], c2, s2, ns2);
}
__device__ __forceinline__ void cnot16(u64* v, int cm, int tm) {
    #pragma unroll
    for (int k = 0; k < 16; k++)
        if ((k & cm) && !(k & tm)) { u64 t = v[k]; v[k] = v[k | tm]; v[k | tm] = t; }
}

// ---------------- fused 2-gate pass ----------------
template<int PB>
__device__ __forceinline__ void fused_pass(u64* stp, uint32_t SB, int gA, int gB, int tid) {
    uint32_t uA = SB + USP_OFF + (uint32_t)gA * 256;
    uint32_t uB = SB + USP_OFF + (uint32_t)gB * 256;
    #pragma unroll 1
    for (int it = 0; it < 2; it++) {
        int grp = tid + it * CT;
        int low = grp & ((1 << PB) - 1);
        int base = ((grp >> PB) << (PB + 4)) | low;
        u64 v[16];
        #pragma unroll
        for (int k = 0; k < 16; k++) v[k] = stp[base + (k << PB)];

        u64 w[16];
        #pragma unroll
        for (int c = 0; c < 4; c++) {
            u64 q0 = iswap(v[4*c+0]), q1 = iswap(v[4*c+1]),
                q2 = iswap(v[4*c+2]), q3 = iswap(v[4*c+3]);
            #pragma unroll
            for (int r = 0; r < 4; r++) {
                u64 x, y; lds128v(uA + (uint32_t)(r*4+c)*16, x, y);
                if (c == 0) {
                    w[4*r+0] = f2fma(y, q0, f2mul(x, v[0]));
                    w[4*r+1] = f2fma(y, q1, f2mul(x, v[1]));
                    w[4*r+2] = f2fma(y, q2, f2mul(x, v[2]));
                    w[4*r+3] = f2fma(y, q3, f2mul(x, v[3]));
                } else {
                    w[4*r+0] = f2fma(y, q0, f2fma(x, v[4*c+0], w[4*r+0]));
                    w[4*r+1] = f2fma(y, q1, f2fma(x, v[4*c+1], w[4*r+1]));
                    w[4*r+2] = f2fma(y, q2, f2fma(x, v[4*c+2], w[4*r+2]));
                    w[4*r+3] = f2fma(y, q3, f2fma(x, v[4*c+3], w[4*r+3]));
                }
            }
        }
        #pragma unroll
        for (int c = 0; c < 4; c++) {
            u64 q0 = iswap(w[0*4+c]), q1 = iswap(w[1*4+c]),
                q2 = iswap(w[2*4+c]), q3 = iswap(w[3*4+c]);
            #pragma unroll
            for (int r = 0; r < 4; r++) {
                u64 x, y; lds128v(uB + (uint32_t)(r*4+c)*16, x, y);
                if (c == 0) {
                    v[0*4+r] = f2fma(y, q0, f2mul(x, w[0*4+0]));
                    v[1*4+r] = f2fma(y, q1, f2mul(x, w[1*4+0]));
                    v[2*4+r] = f2fma(y, q2, f2mul(x, w[2*4+0]));
                    v[3*4+r] = f2fma(y, q3, f2mul(x, w[3*4+0]));
                } else {
                    v[0*4+r] = f2fma(y, q0, f2fma(x, w[0*4+c], v[0*4+r]));
                    v[1*4+r] = f2fma(y, q1, f2fma(x, w[1*4+c], v[1*4+r]));
                    v[2*4+r] = f2fma(y, q2, f2fma(x, w[2*4+c], v[2*4+r]));
                    v[3*4+r] = f2fma(y, q3, f2fma(x, w[3*4+c], v[3*4+r]));
                }
            }
        }
        #pragma unroll
        for (int k = 0; k < 16; k++) stp[base + (k << PB)] = v[k];
    }
}

// ---------------- single gate pass at q=12 (bits 1:0), vectorized ----------------
__device__ __forceinline__ void single_pass0(u64* stp, uint32_t SB, int g, int tid) {
    uint32_t ug = SB + USP_OFF + (uint32_t)g * 256;
    #pragma unroll 1
    for (int it = 0; it < 8; it++) {
        uint32_t ad = SB + (uint32_t)(((tid + it * CT) << 2) << 3);
        u64 a0, a1, a2, a3;
        lds128v(ad, a0, a1);
        lds128v(ad + 16, a2, a3);
        u64 q0 = iswap(a0), q1 = iswap(a1), q2 = iswap(a2), q3 = iswap(a3);
        u64 o[4];
        #pragma unroll
        for (int r = 0; r < 4; r++) {
            u64 x, y;
            lds128v(ug + (uint32_t)(r*4+0)*16, x, y);
            o[r] = f2fma(y, q0, f2mul(x, a0));
            lds128v(ug + (uint32_t)(r*4+1)*16, x, y);
            o[r] = f2fma(y, q1, f2fma(x, a1, o[r]));
            lds128v(ug + (uint32_t)(r*4+2)*16, x, y);
            o[r] = f2fma(y, q2, f2fma(x, a2, o[r]));
            lds128v(ug + (uint32_t)(r*4+3)*16, x, y);
            o[r] = f2fma(y, q3, f2fma(x, a3, o[r]));
        }
        sts128v(ad, o[0], o[1]);
        sts128v(ad + 16, o[2], o[3]);
    }
}

// ---------------- kernel 3: circuit (herm folded into init) ----------------
__global__ void __launch_bounds__(CT, 1)
circuit_kernel(const float* __restrict__ var,
               const float* __restrict__ Wh,
               const float* __restrict__ bh,
               const float* __restrict__ A,
               const float* __restrict__ Bp,
               const float* __restrict__ D,
               float* __restrict__ out) {
    extern __shared__ u64 sm[];
    const uint32_t SB = smem_u32(sm);
    u64* stp    = sm;
    u64* hoffp  = sm + HOFF_I;
    u64* hdiagp = sm + HDIAG_I;
    u64* uspp   = sm + USP_I;
    float* ryp  = (float*)(sm + RY_I);
    float* red  = ryp + 84;          // 16 warps x 11 obs
    float* qout = red + 176;

    const int b = blockIdx.x, tid = threadIdx.x;

    for (int i = tid; i < NGATES * 16; i += CT) {
        int g = i >> 4, e = i & 15;
        float2 ue = g_U[((g << 7) | b) * 16 + e];
        uspp[2*i]   = pk2(ue.x, ue.x);
        uspp[2*i+1] = pk2(ue.y, ue.y);
    }
    // herm build in-CTA: off-diagonal pairs
    for (int i = tid; i < NOBS * 120; i += CT) {
        int w = i / 120, t = i % 120;
        int k = 0, rem = t;
        while (rem >= 15 - k) { rem -= 15 - k; k++; }
        int l = k + 1 + rem;
        int lp = l * (l - 1) / 2 + k;
        hoffp[i] = pk2(__ldg(A + w * 120 + lp), __ldg(Bp + w * 120 + lp));
    }
    for (int i = tid; i < NOBS * 16; i += CT) {
        int w = i >> 4, t = i & 15;
        float dv = (t < 15) ? 2.f * __ldg(D + w * 16 + t + 1) : 0.f;
        hdiagp[i] = pk2(dv, dv);
    }
    for (int i = tid; i < 42; i += CT) {
        float t = var[i] * 0.5f;
        ryp[2*i] = cosf(t); ryp[2*i+1] = sinf(t);
    }
    for (int i = tid; i < DIM; i += CT)
        stp[i] = (i == 0) ? 0x3f800000ULL : 0ULL;
    __syncthreads();

    // ---- 26 SU(4) gates in 14 passes ----
    #pragma unroll 1
    for (int off = 0; off < 26; off += 13) {
        fused_pass<10>(stp, SB, off + 0,  off + 1,  tid); __syncthreads();
        fused_pass<6> (stp, SB, off + 2,  off + 3,  tid); __syncthreads();
        fused_pass<2> (stp, SB, off + 4,  off + 5,  tid); __syncthreads();
        single_pass0  (stp, SB, off + 6,            tid); __syncthreads();
        fused_pass<9> (stp, SB, off + 7,  off + 8,  tid); __syncthreads();
        fused_pass<5> (stp, SB, off + 9,  off + 10, tid); __syncthreads();
        fused_pass<1> (stp, SB, off + 11, off + 12, tid); __syncthreads();
    }

    // ---- 3 variational layers ----
    #pragma unroll 1
    for (int layer = 0; layer < 3; layer++) {
        const float* rc = ryp + layer * 28;
        #pragma unroll 1
        for (int p = 0; p < 3; p++) {
            int lo = 10 - 4 * p, q0 = 4 * p;
            u64 c2[4], s2[4], ns2[4];
            #pragma unroll
            for (int wq = 0; wq < 4; wq++) {
                float c = rc[2*(q0+wq)], s = rc[2*(q0+wq)+1];
                c2[wq] = pk2(c, c); s2[wq] = pk2(s, s); ns2[wq] = pk2(-s, -s);
            }
            #pragma unroll 1
            for (int it = 0; it < 2; it++) {
                int grp = tid + it * CT;
                int low = grp & ((1 << lo) - 1);
                int base = ((grp >> lo) << (lo + 4)) | low;
                u64 v[16];
                #pragma unroll
                for (int k = 0; k < 16; k++) v[k] = stp[base + (k << lo)];
                ry16p(v, 8, c2[0], s2[0], ns2[0]);
                ry16p(v, 4, c2[1], s2[1], ns2[1]);
                ry16p(v, 2, c2[2], s2[2], ns2[2]);
                ry16p(v, 1, c2[3], s2[3], ns2[3]);
                cnot16(v, 8, 4);
                cnot16(v, 2, 1);
                cnot16(v, 4, 2);
                #pragma unroll
                for (int k = 0; k < 16; k++) stp[base + (k << lo)] = v[k];
            }
            __syncthreads();
        }
        {
            float ca = rc[24], sa = rc[25], cb = rc[26], sb = rc[27];
            u64 c12 = pk2(ca, ca), s12 = pk2(sa, sa), ns12 = pk2(-sa, -sa);
            u64 c13 = pk2(cb, cb), s13 = pk2(sb, sb), ns13 = pk2(-sb, -sb);
            #pragma unroll 1
            for (int it = 0; it < 8; it++) {
                uint32_t ad = SB + (uint32_t)(((tid + it * CT) << 2) << 3);
                u64 v0, v1, v2, v3;
                lds128v(ad, v0, v1);
                lds128v(ad + 16, v2, v3);
                rypair(v0, v2, c12, s12, ns12);
                rypair(v1, v3, c12, s12, ns12);
                rypair(v0, v1, c13, s13, ns13);
                rypair(v2, v3, c13, s13, ns13);
                { u64 t = v2; v2 = v3; v3 = t; }
                sts128v(ad, v0, v1);
                sts128v(ad + 16, v2, v3);
            }
            __syncthreads();
        }
        for (int i = tid; i < DIM; i += CT) {
            int j = i;
            if (i & (1 << 10)) j ^= (1 << 9);
            if (i & (1 << 6))  j ^= (1 << 5);
            if (i & (1 << 2))  j ^= (1 << 1);
            if (j > i) { u64 t = stp[i]; stp[i] = stp[j]; stp[j] = t; }
        }
        __syncthreads();
    }

    // ---- 11 expectation values: qa precompute + volatile h loads (proven best) ----
    const int wid = tid >> 5, lid = tid & 31;
    #pragma unroll 1
    for (int w = 0; w < NOBS; w++) {
        int lo = 10 - w;
        uint32_t hob = SB + HOFF_OFF + (uint32_t)w * 960;
        uint32_t hdb = SB + HDIAG_OFF + (uint32_t)w * 128;
        u64 aD = 0, aO0 = 0, aO1 = 0, aO2 = 0, aO3 = 0;
        #pragma unroll 1
        for (int it = 0; it < 2; it++) {
            int grp = tid + it * CT;
            int low = grp & ((1 << lo) - 1);
            int base = ((grp >> lo) << (lo + 4)) | low;
            u64 v[16], qa[16];
            #pragma unroll
            for (int k = 0; k < 16; k++) {
                v[k] = stp[base + (k << lo)];
                qa[k] = jswap(v[k]);
            }
            int p = 0;
            #pragma unroll
            for (int k = 0; k < 16; k++) {
                u64 vx = sp_lo(v[k]), vy = sp_hi(v[k]);
                aD = f2fma(lds64v(hdb + (uint32_t)k * 8), f2mul(v[k], v[k]), aD);
                #pragma unroll
                for (int l = k + 1; l < 16; l++) {
                    u64 z = f2fma(vy, qa[l], f2mul(vx, v[l]));
                    u64 h = lds64v(hob + (uint32_t)p * 8);
                    switch (p & 3) {
                        case 0: aO0 = f2fma(h, z, aO0); break;
                        case 1: aO1 = f2fma(h, z, aO1); break;
                        case 2: aO2 = f2fma(h, z, aO2); break;
                        default: aO3 = f2fma(h, z, aO3); break;
                    }
                    p++;
                }
            }
        }
        u64 aO = f2add(f2add(aO0, aO1), f2add(aO2, aO3));
        float xr, xi, dr, di;
        upk(aO, xr, xi);
        upk(aD, dr, di);
        float acc = fmaf(2.f, xr + xi, dr + di);
        #pragma unroll
        for (int off2 = 16; off2; off2 >>= 1) acc += __shfl_xor_sync(0xffffffffu, acc, off2);
        if (lid == 0) red[wid * NOBS + w] = acc;
    }
    __syncthreads();
    if (tid < NOBS) {
        float t = 0.f;
        #pragma unroll
        for (int i = 0; i < CT / 32; i++) t += red[i * NOBS + tid];
        qout[tid] = t;
    }
    __syncthreads();

    if (tid < 10) {
        float o = bh[tid];
        #pragma unroll
        for (int w = 0; w < NOBS; w++) o = fmaf(qout[w], Wh[tid * NOBS + w], o);
        out[b * 10 + tid] = o;
    }
}

// ---------------- launch ----------------
extern "C" void kernel_launch(void* const* d_in, const int* in_sizes, int n_in,
                              void* d_out, int out_size) {
    const float* x    = (const float*)d_in[0];
    const float* W_e  = (const float*)d_in[1];
    const float* b_e  = (const float*)d_in[2];
    const float* var  = (const float*)d_in[3];
    const float* A    = (const float*)d_in[4];
    const float* Bp   = (const float*)d_in[5];
    const float* D    = (const float*)d_in[6];
    const float* Wh   = (const float*)d_in[7];
    const float* bh   = (const float*)d_in[8];
    float* out = (float*)d_out;

    cudaFuncSetAttribute(circuit_kernel, cudaFuncAttributeMaxDynamicSharedMemorySize, SMEM_BYTES);

    encode_kernel<<<49 * 4, CT>>>(x, W_e, b_e);
    su4_kernel<<<(NGATES * BATCH + 31) / 32, 32>>>();
    circuit_kernel<<<BATCH, CT, SMEM_BYTES>>>(var, Wh, bh, A, Bp, D, out);
}

// round 17
// speedup vs baseline: 1.0237x; 1.0237x over previous
#include <cuda_runtime.h>
#include <stdint.h>

typedef unsigned long long u64;

#define NQ     14
#define DIM    16384
#define BATCH  128
#define NGATES 26
#define NOBS   11
#define ENC    390
#define INDIM  784
#define CT     512

// smem u64-index layout
#define HOFF_I   16384
#define HDIAG_I  (HOFF_I + 1320)
#define USP_I    (HDIAG_I + 176)
#define RY_I     (USP_I + 832)
#define HOFF_OFF  (HOFF_I * 8)
#define HDIAG_OFF (HDIAG_I * 8)
#define USP_OFF   (USP_I * 8)
#define SMEM_BYTES (RY_I * 8 + (84 + 176 + 16) * 4)

// ---------------- device scratch ----------------
__device__ float g_enc[BATCH * ENC];

// ---------------- packed f32x2 helpers ----------------
__device__ __forceinline__ u64 pk2(float lo, float hi) {
    u64 r; asm("mov.b64 %0,{%1,%2};" : "=l"(r) : "f"(lo), "f"(hi)); return r;
}
__device__ __forceinline__ void upk(u64 v, float& lo, float& hi) {
    asm("mov.b64 {%0,%1},%2;" : "=f"(lo), "=f"(hi) : "l"(v));
}
__device__ __forceinline__ u64 f2fma(u64 a, u64 b, u64 c) {
    u64 d; asm("fma.rn.f32x2 %0,%1,%2,%3;" : "=l"(d) : "l"(a), "l"(b), "l"(c)); return d;
}
__device__ __forceinline__ u64 f2mul(u64 a, u64 b) {
    u64 d; asm("mul.rn.f32x2 %0,%1,%2;" : "=l"(d) : "l"(a), "l"(b)); return d;
}
__device__ __forceinline__ u64 f2add(u64 a, u64 b) {
    u64 d; asm("add.rn.f32x2 %0,%1,%2;" : "=l"(d) : "l"(a), "l"(b)); return d;
}
// (re,im) -> (-im, re)
__device__ __forceinline__ u64 iswap(u64 v) {
    u64 r; asm("{.reg .f32 lo,hi,nh; mov.b64 {lo,hi},%1; neg.f32 nh,hi; mov.b64 %0,{nh,lo};}"
               : "=l"(r) : "l"(v)); return r;
}
// (re,im) -> (im, -re)
__device__ __forceinline__ u64 jswap(u64 v) {
    u64 r; asm("{.reg .f32 lo,hi,nl; mov.b64 {lo,hi},%1; neg.f32 nl,lo; mov.b64 %0,{hi,nl};}"
               : "=l"(r) : "l"(v)); return r;
}
__device__ __forceinline__ u64 sp_lo(u64 v) {
    u64 r; asm("{.reg .f32 lo,hi; mov.b64 {lo,hi},%1; mov.b64 %0,{lo,lo};}"
               : "=l"(r) : "l"(v)); return r;
}
__device__ __forceinline__ u64 sp_hi(u64 v) {
    u64 r; asm("{.reg .f32 lo,hi; mov.b64 {lo,hi},%1; mov.b64 %0,{hi,hi};}"
               : "=l"(r) : "l"(v)); return r;
}

// ---------------- shared-memory asm accessors ----------------
__device__ __forceinline__ uint32_t smem_u32(const void* p) {
    uint32_t a;
    asm("{.reg .u64 t; cvta.to.shared.u64 t,%1; cvt.u32.u64 %0,t;}" : "=r"(a) : "l"(p));
    return a;
}
__device__ __forceinline__ u64 lds64v(uint32_t a) {
    u64 r; asm volatile("ld.shared.b64 %0,[%1];" : "=l"(r) : "r"(a)); return r;
}
__device__ __forceinline__ void lds128v(uint32_t a, u64& x, u64& y) {
    asm volatile("ld.shared.v2.b64 {%0,%1},[%2];" : "=l"(x), "=l"(y) : "r"(a));
}
__device__ __forceinline__ void sts128v(uint32_t a, u64 x, u64 y) {
    asm volatile("st.shared.v2.b64 [%0],{%1,%2};" :: "r"(a), "l"(x), "l"(y) : "memory");
}

// ---------------- per-element Pauli contribution map ----------------
// CM[e][t] = {m, re, im}: H[e] = sum_t th[m] * (re + i*im)   (dummy rows have re=im=0)
__constant__ signed char CM[16][4][3] = {
 {{2,1,0},{11,1,0},{14,1,0},{0,0,0}},       // e0  (0,0)
 {{0,1,0},{1,0,-1},{12,1,0},{13,0,-1}},     // e1  (0,1)
 {{3,1,0},{6,1,0},{7,0,-1},{10,0,-1}},      // e2  (0,2)
 {{4,1,0},{5,0,-1},{8,0,-1},{9,-1,0}},      // e3  (0,3)
 {{0,1,0},{1,0,1},{12,1,0},{13,0,1}},       // e4  (1,0)
 {{2,-1,0},{11,1,0},{14,-1,0},{0,0,0}},     // e5  (1,1)
 {{4,1,0},{5,0,1},{8,0,-1},{9,1,0}},        // e6  (1,2)
 {{3,1,0},{6,-1,0},{7,0,-1},{10,0,1}},      // e7  (1,3)
 {{3,1,0},{6,1,0},{7,0,1},{10,0,1}},        // e8  (2,0)
 {{4,1,0},{5,0,-1},{8,0,1},{9,1,0}},        // e9  (2,1)
 {{2,1,0},{11,-1,0},{14,-1,0},{0,0,0}},     // e10 (2,2)
 {{0,1,0},{1,0,-1},{12,-1,0},{13,0,1}},     // e11 (2,3)
 {{4,1,0},{5,0,1},{8,0,1},{9,-1,0}},        // e12 (3,0)
 {{3,1,0},{6,-1,0},{7,0,1},{10,0,-1}},      // e13 (3,1)
 {{0,1,0},{1,0,1},{12,-1,0},{13,0,-1}},     // e14 (3,2)
 {{2,-1,0},{11,-1,0},{14,1,0},{0,0,0}},     // e15 (3,3)
};

// ---------------- kernel 1: encode (392 blocks, 8 j per block, 1 row per warp) ----------------
__global__ void encode_kernel(const float* __restrict__ x,
                              const float* __restrict__ W,
                              const float* __restrict__ bv) {
    __shared__ float4 wrow[8][INDIM / 4];          // 25 KB
    int jt = blockIdx.x % 49;
    int bt = blockIdx.x / 49;
    int j0 = jt * 8;
    for (int i = threadIdx.x; i < 8 * (INDIM / 4); i += CT) {
        int jj = i / (INDIM / 4), kk = i % (INDIM / 4);
        int j = j0 + jj; if (j >= ENC) j = ENC - 1;
        wrow[jj][kk] = ((const float4*)(W + (size_t)j * INDIM))[kk];
    }
    __syncthreads();
    int warp = threadIdx.x >> 5, lane = threadIdx.x & 31;
    int b = bt * 16 + warp;
    const float4* xr = (const float4*)(x + (size_t)b * INDIM);
    float4 xa[7];
    #pragma unroll
    for (int i = 0; i < 7; i++) {
        int idx = lane + 32 * i;
        xa[i] = (idx < INDIM / 4) ? __ldg(xr + idx) : make_float4(0.f, 0.f, 0.f, 0.f);
    }
    float acc[8] = {0.f, 0.f, 0.f, 0.f, 0.f, 0.f, 0.f, 0.f};
    #pragma unroll
    for (int jj = 0; jj < 8; jj++) {
        #pragma unroll
        for (int i = 0; i < 7; i++) {
            int idx = lane + 32 * i;
            if (idx < INDIM / 4) {
                float4 wa = wrow[jj][idx];
                acc[jj] = fmaf(xa[i].x, wa.x, acc[jj]);
                acc[jj] = fmaf(xa[i].y, wa.y, acc[jj]);
                acc[jj] = fmaf(xa[i].z, wa.z, acc[jj]);
                acc[jj] = fmaf(xa[i].w, wa.w, acc[jj]);
            }
        }
    }
    #pragma unroll
    for (int off = 16; off; off >>= 1) {
        #pragma unroll
        for (int jj = 0; jj < 8; jj++)
            acc[jj] += __shfl_xor_sync(0xffffffffu, acc[jj], off);
    }
    if (lane == 0) {
        #pragma unroll
        for (int jj = 0; jj < 8; jj++) {
            int j = j0 + jj;
            if (j < ENC) g_enc[b * ENC + j] = acc[jj] + bv[j];
        }
    }
}

// ---------------- packed RY pair ----------------
__device__ __forceinline__ void rypair(u64& a, u64& b, u64 c2, u64 s2, u64 ns2) {
    u64 na = f2fma(ns2, b, f2mul(c2, a));
    u64 nb = f2fma(c2,  b, f2mul(s2, a));
    a = na; b = nb;
}
__device__ __forceinline__ void ry16p(u64* v, int m, u64 c2, u64 s2, u64 ns2) {
    #pragma unroll
    for (int k = 0; k < 16; k++) if (!(k & m)) rypair(v[k], v[k | m], c2, s2, ns2);
}
__device__ __forceinline__ void cnot16(u64* v, int cm, int tm) {
    #pragma unroll
    for (int k = 0; k < 16; k++)
        if ((k & cm) && !(k & tm)) { u64 t = v[k]; v[k] = v[k | tm]; v[k | tm] = t; }
}

// ---------------- fused 2-gate pass ----------------
template<int PB>
__device__ __forceinline__ void fused_pass(u64* stp, uint32_t SB, int gA, int gB, int tid) {
    uint32_t uA = SB + USP_OFF + (uint32_t)gA * 256;
    uint32_t uB = SB + USP_OFF + (uint32_t)gB * 256;
    #pragma unroll 1
    for (int it = 0; it < 2; it++) {
        int grp = tid + it * CT;
        int low = grp & ((1 << PB) - 1);
        int base = ((grp >> PB) << (PB + 4)) | low;
        u64 v[16];
        #pragma unroll
        for (int k = 0; k < 16; k++) v[k] = stp[base + (k << PB)];

        u64 w[16];
        #pragma unroll
        for (int c = 0; c < 4; c++) {
            u64 q0 = iswap(v[4*c+0]), q1 = iswap(v[4*c+1]),
                q2 = iswap(v[4*c+2]), q3 = iswap(v[4*c+3]);
            #pragma unroll
            for (int r = 0; r < 4; r++) {
                u64 x, y; lds128v(uA + (uint32_t)(r*4+c)*16, x, y);
                if (c == 0) {
                    w[4*r+0] = f2fma(y, q0, f2mul(x, v[0]));
                    w[4*r+1] = f2fma(y, q1, f2mul(x, v[1]));
                    w[4*r+2] = f2fma(y, q2, f2mul(x, v[2]));
                    w[4*r+3] = f2fma(y, q3, f2mul(x, v[3]));
                } else {
                    w[4*r+0] = f2fma(y, q0, f2fma(x, v[4*c+0], w[4*r+0]));
                    w[4*r+1] = f2fma(y, q1, f2fma(x, v[4*c+1], w[4*r+1]));
                    w[4*r+2] = f2fma(y, q2, f2fma(x, v[4*c+2], w[4*r+2]));
                    w[4*r+3] = f2fma(y, q3, f2fma(x, v[4*c+3], w[4*r+3]));
                }
            }
        }
        #pragma unroll
        for (int c = 0; c < 4; c++) {
            u64 q0 = iswap(w[0*4+c]), q1 = iswap(w[1*4+c]),
                q2 = iswap(w[2*4+c]), q3 = iswap(w[3*4+c]);
            #pragma unroll
            for (int r = 0; r < 4; r++) {
                u64 x, y; lds128v(uB + (uint32_t)(r*4+c)*16, x, y);
                if (c == 0) {
                    v[0*4+r] = f2fma(y, q0, f2mul(x, w[0*4+0]));
                    v[1*4+r] = f2fma(y, q1, f2mul(x, w[1*4+0]));
                    v[2*4+r] = f2fma(y, q2, f2mul(x, w[2*4+0]));
                    v[3*4+r] = f2fma(y, q3, f2mul(x, w[3*4+0]));
                } else {
                    v[0*4+r] = f2fma(y, q0, f2fma(x, w[0*4+c], v[0*4+r]));
                    v[1*4+r] = f2fma(y, q1, f2fma(x, w[1*4+c], v[1*4+r]));
                    v[2*4+r] = f2fma(y, q2, f2fma(x, w[2*4+c], v[2*4+r]));
                    v[3*4+r] = f2fma(y, q3, f2fma(x, w[3*4+c], v[3*4+r]));
                }
            }
        }
        #pragma unroll
        for (int k = 0; k < 16; k++) stp[base + (k << PB)] = v[k];
    }
}

// ---------------- single gate pass at q=12 (bits 1:0), vectorized ----------------
__device__ __forceinline__ void single_pass0(u64* stp, uint32_t SB, int g, int tid) {
    uint32_t ug = SB + USP_OFF + (uint32_t)g * 256;
    #pragma unroll 1
    for (int it = 0; it < 8; it++) {
        uint32_t ad = SB + (uint32_t)(((tid + it * CT) << 2) << 3);
        u64 a0, a1, a2, a3;
        lds128v(ad, a0, a1);
        lds128v(ad + 16, a2, a3);
        u64 q0 = iswap(a0), q1 = iswap(a1), q2 = iswap(a2), q3 = iswap(a3);
        u64 o[4];
        #pragma unroll
        for (int r = 0; r < 4; r++) {
            u64 x, y;
            lds128v(ug + (uint32_t)(r*4+0)*16, x, y);
            o[r] = f2fma(y, q0, f2mul(x, a0));
            lds128v(ug + (uint32_t)(r*4+1)*16, x, y);
            o[r] = f2fma(y, q1, f2fma(x, a1, o[r]));
            lds128v(ug + (uint32_t)(r*4+2)*16, x, y);
            o[r] = f2fma(y, q2, f2fma(x, a2, o[r]));
            lds128v(ug + (uint32_t)(r*4+3)*16, x, y);
            o[r] = f2fma(y, q3, f2fma(x, a3, o[r]));
        }
        sts128v(ad, o[0], o[1]);
        sts128v(ad + 16, o[2], o[3]);
    }
}

// ---------------- kernel 2: circuit (expm + herm folded into init) ----------------
__global__ void __launch_bounds__(CT, 1)
circuit_kernel(const float* __restrict__ var,
               const float* __restrict__ Wh,
               const float* __restrict__ bh,
               const float* __restrict__ A,
               const float* __restrict__ Bp,
               const float* __restrict__ D,
               float* __restrict__ out) {
    extern __shared__ u64 sm[];
    const uint32_t SB = smem_u32(sm);
    u64* stp    = sm;
    u64* hoffp  = sm + HOFF_I;
    u64* hdiagp = sm + HDIAG_I;
    u64* uspp   = sm + USP_I;
    float* ryp  = (float*)(sm + RY_I);
    float* red  = ryp + 84;          // 16 warps x 11 obs
    float* qout = red + 176;

    const int b = blockIdx.x, tid = threadIdx.x;
    const int wid = tid >> 5, lid = tid & 31;

    // herm build in-CTA: off-diagonal pairs
    for (int i = tid; i < NOBS * 120; i += CT) {
        int w = i / 120, t = i % 120;
        int k = 0, rem = t;
        while (rem >= 15 - k) { rem -= 15 - k; k++; }
        int l = k + 1 + rem;
        int lp = l * (l - 1) / 2 + k;
        hoffp[i] = pk2(__ldg(A + w * 120 + lp), __ldg(Bp + w * 120 + lp));
    }
    for (int i = tid; i < NOBS * 16; i += CT) {
        int w = i >> 4, t = i & 15;
        float dv = (t < 15) ? 2.f * __ldg(D + w * 16 + t + 1) : 0.f;
        hdiagp[i] = pk2(dv, dv);
    }
    for (int i = tid; i < 42; i += CT) {
        float t = var[i] * 0.5f;
        ryp[2*i] = cosf(t); ryp[2*i+1] = sinf(t);
    }
    for (int i = tid; i < DIM; i += CT)
        stp[i] = (i == 0) ? 0x3f800000ULL : 0ULL;

    // ---- in-CTA warp-parallel SU(4) expm: 2 gates per warp, lane = matrix element ----
    if (wid < 13) {
        int gate = 2 * wid + (lid >> 4);
        int e = lid & 15;
        int hb = lid & 16;                  // half base for shfl sources
        int r = e >> 2, cc = e & 3;
        float diagI = (e % 5 == 0) ? 1.f : 0.f;

        float myth = (e < 15) ? g_enc[b * ENC + gate * 15 + e] : 0.f;
        float2 H = make_float2(0.f, 0.f);
        #pragma unroll
        for (int t = 0; t < 4; t++) {
            int m = CM[e][t][0];
            float thm = __shfl_sync(0xffffffffu, myth, hb + m);
            H.x = fmaf(thm, (float)CM[e][t][1], H.x);
            H.y = fmaf(thm, (float)CM[e][t][2], H.y);
        }
        float fr = H.x * H.x + H.y * H.y;
        #pragma unroll
        for (int o = 8; o; o >>= 1) fr += __shfl_xor_sync(0xffffffffu, fr, o);
        float fro = sqrtf(fr);
        int s = 0; float sc = 1.f;
        while (fro * sc > 0.5f && s < 30) { sc *= 0.5f; s++; }

        float2 Am = make_float2(-H.y * sc, H.x * sc);       // i*H*sc
        float2 R = make_float2(diagI, 0.f);
        #pragma unroll 1
        for (int j = 9; j >= 1; j--) {                       // Tm = Am*R; R = Tm/j + I
            float2 acc = make_float2(0.f, 0.f);
            #pragma unroll
            for (int k = 0; k < 4; k++) {
                float ax = __shfl_sync(0xffffffffu, Am.x, hb + r * 4 + k);
                float ay = __shfl_sync(0xffffffffu, Am.y, hb + r * 4 + k);
                float bx = __shfl_sync(0xffffffffu, R.x,  hb + k * 4 + cc);
                float by = __shfl_sync(0xffffffffu, R.y,  hb + k * 4 + cc);
                acc.x = fmaf(ax, bx, acc.x); acc.x = fmaf(-ay, by, acc.x);
                acc.y = fmaf(ax, by, acc.y); acc.y = fmaf( ay, bx, acc.y);
            }
            float inv = 1.f / (float)j;
            R.x = fmaf(acc.x, inv, diagI);
            R.y = acc.y * inv;
        }
        int smax = s;
        #pragma unroll
        for (int o = 16; o; o >>= 1) smax = max(smax, __shfl_xor_sync(0xffffffffu, smax, o));
        #pragma unroll 1
        for (int t = 0; t < smax; t++) {                     // squaring, converged shfl
            float2 acc = make_float2(0.f, 0.f);
            #pragma unroll
            for (int k = 0; k < 4; k++) {
                float ax = __shfl_sync(0xffffffffu, R.x, hb + r * 4 + k);
                float ay = __shfl_sync(0xffffffffu, R.y, hb + r * 4 + k);
                float bx = __shfl_sync(0xffffffffu, R.x, hb + k * 4 + cc);
                float by = __shfl_sync(0xffffffffu, R.y, hb + k * 4 + cc);
                acc.x = fmaf(ax, bx, acc.x); acc.x = fmaf(-ay, by, acc.x);
                acc.y = fmaf(ax, by, acc.y); acc.y = fmaf( ay, bx, acc.y);
            }
            if (t < s) R = acc;
        }
        uint32_t idx = (uint32_t)(gate * 16 + e);
        uspp[2 * idx]     = pk2(R.x, R.x);
        uspp[2 * idx + 1] = pk2(R.y, R.y);
    }
    __syncthreads();

    // ---- 26 SU(4) gates in 14 passes ----
    #pragma unroll 1
    for (int off = 0; off < 26; off += 13) {
        fused_pass<10>(stp, SB, off + 0,  off + 1,  tid); __syncthreads();
        fused_pass<6> (stp, SB, off + 2,  off + 3,  tid); __syncthreads();
        fused_pass<2> (stp, SB, off + 4,  off + 5,  tid); __syncthreads();
        single_pass0  (stp, SB, off + 6,            tid); __syncthreads();
        fused_pass<9> (stp, SB, off + 7,  off + 8,  tid); __syncthreads();
        fused_pass<5> (stp, SB, off + 9,  off + 10, tid); __syncthreads();
        fused_pass<1> (stp, SB, off + 11, off + 12, tid); __syncthreads();
    }

    // ---- 3 variational layers ----
    #pragma unroll 1
    for (int layer = 0; layer < 3; layer++) {
        const float* rc = ryp + layer * 28;
        #pragma unroll 1
        for (int p = 0; p < 3; p++) {
            int lo = 10 - 4 * p, q0 = 4 * p;
            u64 c2[4], s2[4], ns2[4];
            #pragma unroll
            for (int wq = 0; wq < 4; wq++) {
                float c = rc[2*(q0+wq)], s = rc[2*(q0+wq)+1];
                c2[wq] = pk2(c, c); s2[wq] = pk2(s, s); ns2[wq] = pk2(-s, -s);
            }
            #pragma unroll 1
            for (int it = 0; it < 2; it++) {
                int grp = tid + it * CT;
                int low = grp & ((1 << lo) - 1);
                int base = ((grp >> lo) << (lo + 4)) | low;
                u64 v[16];
                #pragma unroll
                for (int k = 0; k < 16; k++) v[k] = stp[base + (k << lo)];
                ry16p(v, 8, c2[0], s2[0], ns2[0]);
                ry16p(v, 4, c2[1], s2[1], ns2[1]);
                ry16p(v, 2, c2[2], s2[2], ns2[2]);
                ry16p(v, 1, c2[3], s2[3], ns2[3]);
                cnot16(v, 8, 4);
                cnot16(v, 2, 1);
                cnot16(v, 4, 2);
                #pragma unroll
                for (int k = 0; k < 16; k++) stp[base + (k << lo)] = v[k];
            }
            __syncthreads();
        }
        {
            float ca = rc[24], sa = rc[25], cb = rc[26], sb = rc[27];
            u64 c12 = pk2(ca, ca), s12 = pk2(sa, sa), ns12 = pk2(-sa, -sa);
            u64 c13 = pk2(cb, cb), s13 = pk2(sb, sb), ns13 = pk2(-sb, -sb);
            #pragma unroll 1
            for (int it = 0; it < 8; it++) {
                uint32_t ad = SB + (uint32_t)(((tid + it * CT) << 2) << 3);
                u64 v0, v1, v2, v3;
                lds128v(ad, v0, v1);
                lds128v(ad + 16, v2, v3);
                rypair(v0, v2, c12, s12, ns12);
                rypair(v1, v3, c12, s12, ns12);
                rypair(v0, v1, c13, s13, ns13);
                rypair(v2, v3, c13, s13, ns13);
                { u64 t = v2; v2 = v3; v3 = t; }
                sts128v(ad, v0, v1);
                sts128v(ad + 16, v2, v3);
            }
            __syncthreads();
        }
        for (int i = tid; i < DIM; i += CT) {
            int j = i;
            if (i & (1 << 10)) j ^= (1 << 9);
            if (i & (1 << 6))  j ^= (1 << 5);
            if (i & (1 << 2))  j ^= (1 << 1);
            if (j > i) { u64 t = stp[i]; stp[i] = stp[j]; stp[j] = t; }
        }
        __syncthreads();
    }

    // ---- 11 expectation values: qa precompute + volatile h loads (proven best) ----
    #pragma unroll 1
    for (int w = 0; w < NOBS; w++) {
        int lo = 10 - w;
        uint32_t hob = SB + HOFF_OFF + (uint32_t)w * 960;
        uint32_t hdb = SB + HDIAG_OFF + (uint32_t)w * 128;
        u64 aD = 0, aO0 = 0, aO1 = 0, aO2 = 0, aO3 = 0;
        #pragma unroll 1
        for (int it = 0; it < 2; it++) {
            int grp = tid + it * CT;
            int low = grp & ((1 << lo) - 1);
            int base = ((grp >> lo) << (lo + 4)) | low;
            u64 v[16], qa[16];
            #pragma unroll
            for (int k = 0; k < 16; k++) {
                v[k] = stp[base + (k << lo)];
                qa[k] = jswap(v[k]);
            }
            int p = 0;
            #pragma unroll
            for (int k = 0; k < 16; k++) {
                u64 vx = sp_lo(v[k]), vy = sp_hi(v[k]);
                aD = f2fma(lds64v(hdb + (uint32_t)k * 8), f2mul(v[k], v[k]), aD);
                #pragma unroll
                for (int l = k + 1; l < 16; l++) {
                    u64 z = f2fma(vy, qa[l], f2mul(vx, v[l]));
                    u64 h = lds64v(hob + (uint32_t)p * 8);
                    switch (p & 3) {
                        case 0: aO0 = f2fma(h, z, aO0); break;
                        case 1: aO1 = f2fma(h, z, aO1); break;
                        case 2: aO2 = f2fma(h, z, aO2); break;
                        default: aO3 = f2fma(h, z, aO3); break;
                    }
                    p++;
                }
            }
        }
        u64 aO = f2add(f2add(aO0, aO1), f2add(aO2, aO3));
        float xr, xi, dr, di;
        upk(aO, xr, xi);
        upk(aD, dr, di);
        float acc = fmaf(2.f, xr + xi, dr + di);
        #pragma unroll
        for (int off2 = 16; off2; off2 >>= 1) acc += __shfl_xor_sync(0xffffffffu, acc, off2);
        if (lid == 0) red[wid * NOBS + w] = acc;
    }
    __syncthreads();
    if (tid < NOBS) {
        float t = 0.f;
        #pragma unroll
        for (int i = 0; i < CT / 32; i++) t += red[i * NOBS + tid];
        qout[tid] = t;
    }
    __syncthreads();

    if (tid < 10) {
        float o = bh[tid];
        #pragma unroll
        for (int w = 0; w < NOBS; w++) o = fmaf(qout[w], Wh[tid * NOBS + w], o);
        out[b * 10 + tid] = o;
    }
}

// ---------------- launch ----------------
extern "C" void kernel_launch(void* const* d_in, const int* in_sizes, int n_in,
                              void* d_out, int out_size) {
    const float* x    = (const float*)d_in[0];
    const float* W_e  = (const float*)d_in[1];
    const float* b_e  = (const float*)d_in[2];
    const float* var  = (const float*)d_in[3];
    const float* A    = (const float*)d_in[4];
    const float* Bp   = (const float*)d_in[5];
    const float* D    = (const float*)d_in[6];
    const float* Wh   = (const float*)d_in[7];
    const float* bh   = (const float*)d_in[8];
    float* out = (float*)d_out;

    cudaFuncSetAttribute(circuit_kernel, cudaFuncAttributeMaxDynamicSharedMemorySize, SMEM_BYTES);

    encode_kernel<<<49 * 8, CT>>>(x, W_e, b_e);
    circuit_kernel<<<BATCH, CT, SMEM_BYTES>>>(var, Wh, bh, A, Bp, D, out);
}